// round 2
// baseline (speedup 1.0000x reference)
#include <cuda_runtime.h>

// ConvNearestNeightbor: out[b, n*C+c, h, w] = max_k |x_pad[b,c,h-row,w-col] - nb[n,c,k]|
// Issue-slot-bound: minimize warp instructions via packed f32x2 adds + dual-abs FMNMX trees.

namespace {

constexpr int B = 16, C = 32, H = 32, W = 32, NUM = 32;
constexpr int HW = H * W;
constexpr int NSPLIT = 2;
constexpr int NPER = NUM / NSPLIT;  // 16

__device__ __forceinline__ unsigned long long addx2(unsigned long long a, unsigned long long b) {
  unsigned long long r;
  asm("add.rn.f32x2 %0, %1, %2;" : "=l"(r) : "l"(a), "l"(b));
  return r;
}
__device__ __forceinline__ unsigned long long pack2(float lo, float hi) {
  unsigned long long r;
  asm("mov.b64 %0, {%1, %2};" : "=l"(r) : "f"(lo), "f"(hi));
  return r;
}
__device__ __forceinline__ void unp2(unsigned long long v, float& lo, float& hi) {
  asm("mov.b64 {%0, %1}, %2;" : "=f"(lo), "=f"(hi) : "l"(v));
}
// max(|a|,|b|) -> single FMNMX with abs modifiers on both sources
__device__ __forceinline__ float maxabs(float a, float b) {
  return fmaxf(fabsf(a), fabsf(b));
}
// max over 9 values' abs: 8 FMNMX, depth 4
__device__ __forceinline__ float maxabs9(const float* v) {
  float t0 = maxabs(v[0], v[1]);
  float t1 = maxabs(v[2], v[3]);
  float t2 = maxabs(v[4], v[5]);
  float t3 = maxabs(v[6], v[7]);
  float u0 = fmaxf(t0, t1);
  float u1 = fmaxf(t2, t3);
  return fmaxf(fmaxf(u0, u1), fabsf(v[8]));
}

__global__ __launch_bounds__(256) void cnn_kernel(
    const float* __restrict__ x,
    const float* __restrict__ nb,
    float* __restrict__ out) {
  __shared__ __align__(16) float xs[34 * 36];          // 34x34 halo tile, padded rows
  __shared__ __align__(8) float2 nbs2[NPER][9];        // negated + duplicated for LDS.64

  const int bc = blockIdx.x;   // 0 .. B*C-1
  const int ns = blockIdx.y;   // 0 .. NSPLIT-1
  const int c  = bc & (C - 1);
  const int b  = bc / C;
  const int tid = threadIdx.x;

  // ---- load x tile with zero halo ----
  const float* xp = x + (size_t)bc * HW;
  for (int i = tid; i < 34 * 34; i += 256) {
    int r  = i / 34;
    int cc = i - r * 34;
    int gh = r - 1, gw = cc - 1;
    float v = 0.f;
    if ((unsigned)gh < (unsigned)H && (unsigned)gw < (unsigned)W)
      v = xp[gh * W + gw];
    xs[r * 36 + cc] = v;
  }
  // ---- load neighbors: negate + duplicate so LDS.64 gives {-nk,-nk} ready to add ----
  for (int i = tid; i < NPER * 9; i += 256) {
    int nn = i / 9;
    int k  = i - nn * 9;
    float v = -nb[(size_t)(ns * NPER + nn) * (C * 9) + c * 9 + k];
    nbs2[nn][k] = make_float2(v, v);
  }
  __syncthreads();

  // thread -> 4 consecutive w outputs at row h
  const int h  = tid >> 3;          // 0..31
  const int wq = (tid & 7) << 2;    // 0,4,...,28

  // hoist 3x6 x-window, pre-packed into the 5 sliding pairs per row:
  // pr[r][j] = {xs[h+r][wq+j], xs[h+r][wq+j+1]}, j=0..4
  unsigned long long pr[3][5];
#pragma unroll
  for (int r = 0; r < 3; r++) {
    const float* p = &xs[(h + r) * 36 + wq];
    float4 v4 = *(const float4*)p;
    float2 v2 = *(const float2*)(p + 4);
    float xv0 = v4.x, xv1 = v4.y, xv2 = v4.z, xv3 = v4.w, xv4 = v2.x, xv5 = v2.y;
    pr[r][0] = pack2(xv0, xv1);
    pr[r][1] = pack2(xv1, xv2);
    pr[r][2] = pack2(xv2, xv3);
    pr[r][3] = pack2(xv3, xv4);
    pr[r][4] = pack2(xv4, xv5);
  }

  float* outp = out + ((size_t)(b * NUM + ns * NPER) * C + c) * HW + h * W + wq;

#pragma unroll 2
  for (int nn = 0; nn < NPER; nn++) {
    // q0..q3: per-output diffs across the 9 taps
    float q0[9], q1[9], q2[9], q3[9];
#pragma unroll
    for (int k = 0; k < 9; k++) {
      const int r  = 2 - k / 3;   // row = 1 - r
      const int cc = 2 - k % 3;   // col = 1 - cc
      unsigned long long nk2 =
          *(const unsigned long long*)&nbs2[nn][k];      // LDS.64 broadcast
      unsigned long long dA = addx2(pr[r][cc],     nk2); // outputs 0,1
      unsigned long long dB = addx2(pr[r][cc + 2], nk2); // outputs 2,3
      unp2(dA, q0[k], q1[k]);
      unp2(dB, q2[k], q3[k]);
    }
    *(float4*)outp = make_float4(maxabs9(q0), maxabs9(q1), maxabs9(q2), maxabs9(q3));
    outp += (size_t)C * HW;  // next n
  }
}

}  // namespace

extern "C" void kernel_launch(void* const* d_in, const int* in_sizes, int n_in,
                              void* d_out, int out_size) {
  const float* x  = (const float*)d_in[0];   // (B,C,H,W) fp32
  const float* nb = (const float*)d_in[1];   // (NUM,C,9) fp32
  float* out = (float*)d_out;                // (B, NUM*C, H, W) fp32
  dim3 grid(B * C, NSPLIT);
  cnn_kernel<<<grid, 256>>>(x, nb, out);
}

// round 3
// speedup vs baseline: 1.2691x; 1.2691x over previous
#include <cuda_runtime.h>

// ConvNearestNeightbor: out[b, n*C+c, h, w] = max_k |x_pad[b,c,h-row,w-col] - nb[n,c,k]|
// Issue-slot-bound. Scalar FADD + dual-abs FMNMX tree (8/output), vectorized prologue.

namespace {

constexpr int B = 16, C = 32, H = 32, W = 32, NUM = 32;
constexpr int HW = H * W;
constexpr int NSPLIT = 2;
constexpr int NPER = NUM / NSPLIT;  // 16

// max(|a|,|b|) -> single FMNMX with |src| modifiers on both operands
__device__ __forceinline__ float maxabs(float a, float b) {
  return fmaxf(fabsf(a), fabsf(b));
}

__global__ __launch_bounds__(256) void cnn_kernel(
    const float* __restrict__ x,
    const float* __restrict__ nb,
    float* __restrict__ out) {
  __shared__ __align__(16) float xs[34 * 36];      // halo tile, padded rows (36 floats)
  __shared__ __align__(16) float nbs[NPER * 12];   // 9 taps padded to 12 -> LDS.128

  const int bc = blockIdx.x;   // 0 .. B*C-1
  const int ns = blockIdx.y;   // 0 .. NSPLIT-1
  const int c  = bc & (C - 1);
  const int b  = bc / C;
  const int tid = threadIdx.x;

  const int h  = tid >> 3;          // 0..31  (also interior-load row)
  const int wq = (tid & 7) << 2;    // 0,4,...,28

  // ---- prologue: 1 vector LDG per thread + predicated halo zeros ----
  const float* xp = x + (size_t)bc * HW;
  {
    float4 v = *(const float4*)(xp + h * W + wq);
    float* dst = &xs[(h + 1) * 36 + wq + 1];
    dst[0] = v.x; dst[1] = v.y; dst[2] = v.z; dst[3] = v.w;
  }
  if (tid < 132) {  // halo cells: rows 0,33 cols 0..33; cols 0,33 rows 1..32
    int rr, cc;
    if (tid < 68)        { rr = (tid < 34) ? 0 : 33; cc = (tid < 34) ? tid : tid - 34; }
    else if (tid < 100)  { rr = tid - 68 + 1;  cc = 0; }
    else                 { rr = tid - 100 + 1; cc = 33; }
    xs[rr * 36 + cc] = 0.f;
  }
  if (tid < NPER * 9) {  // 144 neighbor scalars
    int nn = tid / 9;
    int k  = tid - nn * 9;
    nbs[nn * 12 + k] = nb[(size_t)(ns * NPER + nn) * (C * 9) + c * 9 + k];
  }
  __syncthreads();

  // hoist the 3x6 x-window into registers (reused across all NPER n)
  float xv[3][6];
#pragma unroll
  for (int r = 0; r < 3; r++) {
    const float* p = &xs[(h + r) * 36 + wq];
    float4 v4 = *(const float4*)p;
    float2 v2 = *(const float2*)(p + 4);
    xv[r][0] = v4.x; xv[r][1] = v4.y; xv[r][2] = v4.z; xv[r][3] = v4.w;
    xv[r][4] = v2.x; xv[r][5] = v2.y;
  }

  float* outp = out + ((size_t)(b * NUM + ns * NPER) * C + c) * HW + h * W + wq;

#pragma unroll 4
  for (int nn = 0; nn < NPER; nn++) {
    float4 n0 = *(const float4*)&nbs[nn * 12];
    float4 n1 = *(const float4*)&nbs[nn * 12 + 4];
    float  n8 = nbs[nn * 12 + 8];
    const float nv[9] = {n0.x, n0.y, n0.z, n0.w, n1.x, n1.y, n1.z, n1.w, n8};

    float res[4];
#pragma unroll
    for (int j = 0; j < 4; j++) {
      // tap k -> window coords: r = 2 - k/3, cc = 2 - k%3, read xv[r][cc+j]
      float d[9];
#pragma unroll
      for (int k = 0; k < 9; k++) {
        const int r  = 2 - k / 3;
        const int cc = 2 - k % 3;
        d[k] = xv[r][cc + j] - nv[k];
      }
      // 8-op dual-abs max tree, depth 4
      float t0 = maxabs(d[0], d[1]);
      float t1 = maxabs(d[2], d[3]);
      float t2 = maxabs(d[4], d[5]);
      float t3 = maxabs(d[6], d[7]);
      float u0 = fmaxf(t0, t1);
      float u1 = fmaxf(t2, t3);
      res[j] = fmaxf(u0, fmaxf(u1, fabsf(d[8])));
    }
    *(float4*)outp = make_float4(res[0], res[1], res[2], res[3]);
    outp += (size_t)C * HW;  // next n: channel index advances by C
  }
}

}  // namespace

extern "C" void kernel_launch(void* const* d_in, const int* in_sizes, int n_in,
                              void* d_out, int out_size) {
  const float* x  = (const float*)d_in[0];   // (B,C,H,W) fp32
  const float* nb = (const float*)d_in[1];   // (NUM,C,9) fp32
  float* out = (float*)d_out;                // (B, NUM*C, H, W) fp32
  dim3 grid(B * C, NSPLIT);
  cnn_kernel<<<grid, 256>>>(x, nb, out);
}